// round 8
// baseline (speedup 1.0000x reference)
#include <cuda_runtime.h>
#include <cstdint>

#define NN 512      // tokens
#define DN 256      // d_node
#define DE 128      // d_edge
#define DH 32       // d_head
#define LN_EPS 1e-5f
#define NBLOCKS 148 // persistent blocks (<= SM count; GB300 has 152)
#define NGRP 37     // 37 n-groups x 4 m-tiles = 148

// Scratch (device globals: no allocation allowed)
__device__ float g_left[NN * DH];
__device__ float g_right[NN * DH];
__device__ float g_T[NN * DH * DE];   // [n][j][e] = [512][32][128]
__device__ unsigned g_bar1, g_bar2;   // grid-barrier counters (reset per launch)

// ---------------- packed f32x2 helpers (sm_103a) ----------------
__device__ __forceinline__ unsigned long long pk2(float lo, float hi) {
    unsigned long long r;
    asm("mov.b64 %0, {%1, %2};" : "=l"(r) : "f"(lo), "f"(hi));
    return r;
}
__device__ __forceinline__ void fma2(unsigned long long& d,
                                     unsigned long long a,
                                     unsigned long long b) {
    asm("fma.rn.f32x2 %0, %1, %2, %0;" : "+l"(d) : "l"(a), "l"(b));
}
__device__ __forceinline__ void upk2(unsigned long long v, float& lo, float& hi) {
    asm("mov.b64 {%0, %1}, %2;" : "=f"(lo), "=f"(hi) : "l"(v));
}

// ---------------- cp.async helpers ----------------
__device__ __forceinline__ void cp_async16(unsigned smem_addr, const void* gptr) {
    asm volatile("cp.async.cg.shared.global [%0], [%1], 16;"
                 :: "r"(smem_addr), "l"(gptr));
}
__device__ __forceinline__ void cp_commit() {
    asm volatile("cp.async.commit_group;");
}
__device__ __forceinline__ void cp_wait_all() {
    asm volatile("cp.async.wait_group 0;");
}

// ---------------- grid barrier (monotonic counter, reset externally) ------
__device__ __forceinline__ void grid_barrier(unsigned* bar, unsigned target) {
    __syncthreads();                 // all block threads' stores HB thread 0
    if (threadIdx.x == 0) {
        __threadfence();             // publish this block's writes
        atomicAdd(bar, 1u);
        while (atomicAdd(bar, 0u) < target) { __nanosleep(64); }
    }
    __syncthreads();
    __threadfence();                 // acquire: see other blocks' writes
}

// ---------------- reset kernel (runs before fused each launch) ------------
__global__ void reset_kernel() { g_bar1 = 0; g_bar2 = 0; }

// ---------------- fused persistent kernel ----------------
__global__ void __launch_bounds__(512, 1)
fused_kernel(const float* __restrict__ node,
             const float* __restrict__ edge,
             const float* __restrict__ ln_w,
             const float* __restrict__ ln_b,
             const float* __restrict__ wl,
             const float* __restrict__ bl,
             const float* __restrict__ wr,
             const float* __restrict__ br,
             const float* __restrict__ w_out,
             const float* __restrict__ b_out,
             float* __restrict__ out) {
    __shared__ __align__(16) char sm[49152];   // 48 KB, phase-aliased

    int tid = threadIdx.x;
    int bid = blockIdx.x;

    // ===================== PHASE 1: LayerNorm + projections ================
    // Blocks 0..127 each handle 4 tokens; 128 threads per token.
    if (bid < 128) {
        float*  xs  = (float*)sm;                 // [4][256]
        float2* red = (float2*)(sm + 4096);       // [4 groups][4 warps]
        float*  ps  = (float*)(sm + 4352);        // [4 groups][2 parts][64]

        int grpT = tid >> 7;          // token group 0..3
        int t    = tid & 127;
        int n    = bid * 4 + grpT;

        const float* np = node + n * DN;
        float v0 = np[t], v1 = np[t + 128];

        float s = v0 + v1, q = v0 * v0 + v1 * v1;
        #pragma unroll
        for (int o = 16; o; o >>= 1) {
            s += __shfl_xor_sync(0xffffffffu, s, o);
            q += __shfl_xor_sync(0xffffffffu, q, o);
        }
        if ((t & 31) == 0) red[grpT * 4 + (t >> 5)] = make_float2(s, q);
        __syncthreads();
        float S = 0.f, Q = 0.f;
        #pragma unroll
        for (int i = 0; i < 4; i++) {
            float2 rv = red[grpT * 4 + i];
            S += rv.x; Q += rv.y;
        }
        float mu = S * (1.f / 256.f);
        float var = Q * (1.f / 256.f) - mu * mu;
        float rstd = rsqrtf(var + LN_EPS);

        xs[grpT * 256 + t]       = (v0 - mu) * rstd * ln_w[t] + ln_b[t];
        xs[grpT * 256 + t + 128] = (v1 - mu) * rstd * ln_w[t + 128] + ln_b[t + 128];
        __syncthreads();

        int h = t & 31;
        int sel = (t >> 5) & 1;
        int part = t >> 6;            // 0..1, halves of 128 k each
        const float* __restrict__ w = sel ? wr : wl;
        const float* xk = xs + grpT * 256 + part * 128;
        const float* wk = w + part * 128 * DH + h;
        float a0 = 0.f, a1 = 0.f, a2 = 0.f, a3 = 0.f;
        #pragma unroll 4
        for (int k = 0; k < 128; k += 4) {
            a0 += xk[k + 0] * wk[(k + 0) * DH];
            a1 += xk[k + 1] * wk[(k + 1) * DH];
            a2 += xk[k + 2] * wk[(k + 2) * DH];
            a3 += xk[k + 3] * wk[(k + 3) * DH];
        }
        ps[(grpT * 2 + part) * 64 + sel * 32 + h] = (a0 + a1) + (a2 + a3);
        __syncthreads();

        if (t < 64) {
            float r = ps[(grpT * 2 + 0) * 64 + t] + ps[(grpT * 2 + 1) * 64 + t];
            if (t < 32) g_left[n * DH + t] = r + bl[t];
            else        g_right[n * DH + (t - 32)] = r + br[t - 32];
        }
    }

    grid_barrier(&g_bar1, NBLOCKS);

    // ===================== PHASE 2: T = left @ w_out ========================
    // 512 units of [32 n][128 col], strided over blocks. 512 threads/unit.
    {
        float* As = (float*)sm;       // [32 n][32 i] = 4 KB
        for (unsigned u = bid; u < 512; u += NBLOCKS) {
            int nb = (int)(u >> 5) * 32;
            int cb = (int)(u & 31) * 128;

            // g_left rows nb..nb+32 are contiguous 1024 floats
            As[tid]       = g_left[nb * DH + tid];
            As[tid + 512] = g_left[nb * DH + tid + 512];
            __syncthreads();

            int col = cb + (tid & 127);
            int nset = tid >> 7;      // 0..3 -> 8 rows each
            float acc[8];
            #pragma unroll
            for (int r = 0; r < 8; r++) acc[r] = 0.f;

            #pragma unroll 4
            for (int i = 0; i < 32; i++) {
                float b = w_out[i * 4096 + col];
                #pragma unroll
                for (int r = 0; r < 8; r++)
                    acc[r] += As[(nset * 8 + r) * 32 + i] * b;
            }
            #pragma unroll
            for (int r = 0; r < 8; r++)
                g_T[(size_t)(nb + nset * 8 + r) * (DH * DE) + col] = acc[r];
            __syncthreads();
        }
    }

    grid_barrier(&g_bar2, NBLOCKS);

    // ===================== PHASE 3: out = edge + b_out + right @ T =========
    // Per block: m-tile fixed, ~14 n. sR once; sT cp.async double-buffered;
    // edge prefetched into regs one n ahead. (R5 body, measured ~62 us.)
    {
        float* sR = (float*)sm;                   // [j][m_local] 16 KB
        float* sT = (float*)(sm + 16384);         // [2][j][e]   32 KB
        unsigned sT_base = (unsigned)__cvta_generic_to_shared(sT);

        int m_tile = bid & 3;
        int grp    = bid >> 2;                    // 0..36
        int n0 = (grp * NN) / NGRP;
        int n1 = ((grp + 1) * NN) / NGRP;
        int m_base = m_tile * 128;
        int lane = tid & 31;
        int w    = tid >> 5;          // 0..15
        int e0 = lane * 4;
        int mt = w * 8;

        // preload sT[n0] into buf 0
        {
            const char* g = (const char*)(g_T + (size_t)n0 * (DH * DE)) + tid * 16;
            cp_async16(sT_base + tid * 16, g);
            cp_async16(sT_base + tid * 16 + 8192, g + 8192);
            cp_commit();
        }

        // preload edge[n0] into registers (streaming)
        float4 ev[8];
        {
            const float4* erow = (const float4*)(edge + ((size_t)n0 * NN + m_base + mt) * DE + e0);
            #pragma unroll
            for (int r = 0; r < 8; r++) ev[r] = __ldcs(erow + r * (DE / 4));
        }

        // fill sR (once): sR[j][ml] = right[m_base+ml][j]
        {
            int ml = tid & 127;
            #pragma unroll
            for (int it = 0; it < 2; it++) {
                int jq = (tid >> 7) + it * 4;
                float4 r4 = *(const float4*)(g_right + (m_base + ml) * DH + jq * 4);
                sR[(jq * 4 + 0) * 128 + ml] = r4.x;
                sR[(jq * 4 + 1) * 128 + ml] = r4.y;
                sR[(jq * 4 + 2) * 128 + ml] = r4.z;
                sR[(jq * 4 + 3) * 128 + ml] = r4.w;
            }
        }

        float4 b4 = *(const float4*)(b_out + e0);

        cp_wait_all();
        __syncthreads();

        int buf = 0;
        for (int n = n0; n < n1; n++, buf ^= 1) {
            bool more = (n + 1 < n1);

            if (more) {
                const char* g = (const char*)(g_T + (size_t)(n + 1) * (DH * DE)) + tid * 16;
                unsigned sb = sT_base + (buf ^ 1) * (DH * DE * 4) + tid * 16;
                cp_async16(sb, g);
                cp_async16(sb + 8192, g + 8192);
                cp_commit();
            }

            unsigned long long acc[4][4];
            #pragma unroll
            for (int mp = 0; mp < 4; mp++) {
                float4 ea = ev[2 * mp];
                float4 eb = ev[2 * mp + 1];
                acc[mp][0] = pk2(ea.x + b4.x, eb.x + b4.x);
                acc[mp][1] = pk2(ea.y + b4.y, eb.y + b4.y);
                acc[mp][2] = pk2(ea.z + b4.z, eb.z + b4.z);
                acc[mp][3] = pk2(ea.w + b4.w, eb.w + b4.w);
            }

            if (more) {
                const float4* erow = (const float4*)(edge + ((size_t)(n + 1) * NN + m_base + mt) * DE + e0);
                #pragma unroll
                for (int r = 0; r < 8; r++) ev[r] = __ldcs(erow + r * (DE / 4));
            }

            const float* sTb = sT + buf * (DH * DE);
            #pragma unroll 8
            for (int j = 0; j < DH; j++) {
                float4 t4 = *(const float4*)(sTb + j * DE + e0);
                unsigned long long t0 = pk2(t4.x, t4.x);
                unsigned long long t1 = pk2(t4.y, t4.y);
                unsigned long long t2 = pk2(t4.z, t4.z);
                unsigned long long t3 = pk2(t4.w, t4.w);
                const ulonglong2* rj = (const ulonglong2*)(sR + j * 128 + mt);
                ulonglong2 rA = rj[0];
                ulonglong2 rB = rj[1];
                fma2(acc[0][0], rA.x, t0); fma2(acc[0][1], rA.x, t1);
                fma2(acc[0][2], rA.x, t2); fma2(acc[0][3], rA.x, t3);
                fma2(acc[1][0], rA.y, t0); fma2(acc[1][1], rA.y, t1);
                fma2(acc[1][2], rA.y, t2); fma2(acc[1][3], rA.y, t3);
                fma2(acc[2][0], rB.x, t0); fma2(acc[2][1], rB.x, t1);
                fma2(acc[2][2], rB.x, t2); fma2(acc[2][3], rB.x, t3);
                fma2(acc[3][0], rB.y, t0); fma2(acc[3][1], rB.y, t1);
                fma2(acc[3][2], rB.y, t2); fma2(acc[3][3], rB.y, t3);
            }

            float* orow = out + ((size_t)n * NN + m_base + mt) * DE + e0;
            #pragma unroll
            for (int mp = 0; mp < 4; mp++) {
                float a0, c0, a1, c1, a2, c2, a3, c3;
                upk2(acc[mp][0], a0, c0);
                upk2(acc[mp][1], a1, c1);
                upk2(acc[mp][2], a2, c2);
                upk2(acc[mp][3], a3, c3);
                __stcs((float4*)(orow + (2 * mp) * DE),     make_float4(a0, a1, a2, a3));
                __stcs((float4*)(orow + (2 * mp + 1) * DE), make_float4(c0, c1, c2, c3));
            }

            if (more) {
                cp_wait_all();
                __syncthreads();
            }
        }
    }
}

// ---------------- launch ----------------
extern "C" void kernel_launch(void* const* d_in, const int* in_sizes, int n_in,
                              void* d_out, int out_size) {
    const float* node   = (const float*)d_in[0];
    const float* edge   = (const float*)d_in[1];
    const float* ln_w   = (const float*)d_in[2];
    const float* ln_b   = (const float*)d_in[3];
    const float* w_left = (const float*)d_in[4];
    const float* b_left = (const float*)d_in[5];
    const float* w_right= (const float*)d_in[6];
    const float* b_right= (const float*)d_in[7];
    const float* w_out  = (const float*)d_in[8];
    const float* b_out  = (const float*)d_in[9];
    float* out = (float*)d_out;

    reset_kernel<<<1, 1>>>();
    fused_kernel<<<NBLOCKS, 512>>>(node, edge, ln_w, ln_b, w_left, b_left,
                                   w_right, b_right, w_out, b_out, out);
}

// round 9
// speedup vs baseline: 1.1684x; 1.1684x over previous
#include <cuda_runtime.h>
#include <cstdint>

#define NN 512      // tokens
#define DN 256      // d_node
#define DE 128      // d_edge
#define DH 32       // d_head
#define LN_EPS 1e-5f

// Scratch (device globals: no allocation allowed)
__device__ float g_left[NN * DH];
__device__ float g_right[NN * DH];
__device__ float g_T[NN * DH * DE];   // [n][j][e] = [512][32][128]

// ---------------- packed f32x2 helpers (sm_103a) ----------------
__device__ __forceinline__ unsigned long long pk2(float lo, float hi) {
    unsigned long long r;
    asm("mov.b64 %0, {%1, %2};" : "=l"(r) : "f"(lo), "f"(hi));
    return r;
}
__device__ __forceinline__ void fma2(unsigned long long& d,
                                     unsigned long long a,
                                     unsigned long long b) {
    asm("fma.rn.f32x2 %0, %1, %2, %0;" : "+l"(d) : "l"(a), "l"(b));
}
__device__ __forceinline__ void upk2(unsigned long long v, float& lo, float& hi) {
    asm("mov.b64 {%0, %1}, %2;" : "=f"(lo), "=f"(hi) : "l"(v));
}

// ---------------- P1: LayerNorm + left/right projections ----------------
// One block per token (512 blocks x 256 threads). Fused sum/sumsq reduction.
__global__ void p1_kernel(const float* __restrict__ node,
                          const float* __restrict__ ln_w,
                          const float* __restrict__ ln_b,
                          const float* __restrict__ wl,
                          const float* __restrict__ bl,
                          const float* __restrict__ wr,
                          const float* __restrict__ br) {
    __shared__ float xs[DN];
    __shared__ float2 red[8];
    __shared__ float ps[4][64];

    int n = blockIdx.x;
    int tid = threadIdx.x;
    float v = node[n * DN + tid];

    float s = v, q = v * v;
    #pragma unroll
    for (int o = 16; o; o >>= 1) {
        s += __shfl_xor_sync(0xffffffffu, s, o);
        q += __shfl_xor_sync(0xffffffffu, q, o);
    }
    if ((tid & 31) == 0) red[tid >> 5] = make_float2(s, q);
    __syncthreads();
    float S = 0.f, Q = 0.f;
    #pragma unroll
    for (int i = 0; i < 8; i++) { S += red[i].x; Q += red[i].y; }
    float mu = S * (1.f / 256.f);
    float var = Q * (1.f / 256.f) - mu * mu;
    float rstd = rsqrtf(var + LN_EPS);

    xs[tid] = (v - mu) * rstd * ln_w[tid] + ln_b[tid];
    __syncthreads();

    int h = tid & 31;
    int sel = (tid >> 5) & 1;
    int part = tid >> 6;
    const float* __restrict__ w = sel ? wr : wl;
    int k0 = part * 64;
    float a0 = 0.f, a1 = 0.f, a2 = 0.f, a3 = 0.f;
    #pragma unroll 4
    for (int k = 0; k < 64; k += 4) {
        a0 += xs[k0 + k + 0] * w[(k0 + k + 0) * DH + h];
        a1 += xs[k0 + k + 1] * w[(k0 + k + 1) * DH + h];
        a2 += xs[k0 + k + 2] * w[(k0 + k + 2) * DH + h];
        a3 += xs[k0 + k + 3] * w[(k0 + k + 3) * DH + h];
    }
    ps[part][sel * 32 + h] = (a0 + a1) + (a2 + a3);
    __syncthreads();

    if (tid < 64) {
        float r = ps[0][tid] + ps[1][tid] + ps[2][tid] + ps[3][tid];
        if (tid < 32) g_left[n * DH + tid] = r + bl[tid];
        else          g_right[n * DH + (tid - 32)] = r + br[tid - 32];
    }
}

// ---------------- P2: T = left @ w_out (viewed [32][4096]) ----------------
__global__ void p2_kernel(const float* __restrict__ w_out) {
    __shared__ float As[32 * 32];

    int nb = blockIdx.y * 32;
    int cb = blockIdx.x * 128;
    int tid = threadIdx.x;

    {
        int row = tid >> 3, qq = tid & 7;
        *(float4*)&As[row * 32 + qq * 4] =
            *(const float4*)(g_left + (nb + row) * DH + qq * 4);
    }
    __syncthreads();

    int col = cb + (tid & 127);
    int nset = tid >> 7;
    float acc[16];
    #pragma unroll
    for (int r = 0; r < 16; r++) acc[r] = 0.f;

    #pragma unroll 4
    for (int i = 0; i < 32; i++) {
        float b = w_out[i * 4096 + col];
        #pragma unroll
        for (int r = 0; r < 16; r++)
            acc[r] += As[(nset * 16 + r) * 32 + i] * b;
    }

    #pragma unroll
    for (int r = 0; r < 16; r++)
        g_T[(nb + nset * 16 + r) * (DH * DE) + col] = acc[r];
}

// ---------------- Main kernel: out = edge + b_out + right @ T ----------------
// 64m x 128e tile, 256 threads, 3 blocks/SM (24 warps) -> independent blocks
// interleave their load/compute/store phases on each SM.
// Per thread: 8m x 4e as 16 packed f32x2 accumulators.
__global__ void __launch_bounds__(256, 3)
outk_kernel(const float* __restrict__ edge,
            const float* __restrict__ b_out,
            float* __restrict__ out) {
    __shared__ __align__(16) float sT[DH * DE];   // [j][e]   16 KB
    __shared__ __align__(16) float sR[DH * 64];   // [j][m]    8 KB

    int n = blockIdx.y;
    int m_base = blockIdx.x * 64;
    int tid = threadIdx.x;
    int lane = tid & 31;
    int w    = tid >> 5;          // 0..7
    int e0 = lane * 4;            // 4 e columns
    int mt = w * 8;               // 8 m rows per warp

    // 1) edge loads first (streaming; in flight during smem fills)
    const float4* ep = (const float4*)(edge + ((size_t)n * NN + m_base + mt) * DE + e0);
    float4 ev[8];
    #pragma unroll
    for (int r = 0; r < 8; r++) ev[r] = __ldcs(ep + r * (DE / 4));

    // 2) fill sT (16 KB coalesced: 4 float4 per thread)
    {
        const float4* gT4 = (const float4*)(g_T + (size_t)n * (DH * DE));
        float4* sT4 = (float4*)sT;
        #pragma unroll
        for (int k = 0; k < 4; k++) sT4[tid + k * 256] = gT4[tid + k * 256];
    }
    // 3) fill sR transposed: sR[j][ml] = right[m_base+ml][j]
    {
        int ml = tid & 63;
        int jq0 = tid >> 6;           // 0..3
        #pragma unroll
        for (int it = 0; it < 2; it++) {
            int jq = jq0 + it * 4;    // 0..7
            float4 r4 = *(const float4*)(g_right + (m_base + ml) * DH + jq * 4);
            sR[(jq * 4 + 0) * 64 + ml] = r4.x;
            sR[(jq * 4 + 1) * 64 + ml] = r4.y;
            sR[(jq * 4 + 2) * 64 + ml] = r4.z;
            sR[(jq * 4 + 3) * 64 + ml] = r4.w;
        }
    }
    __syncthreads();

    // 4) acc init from edge + bias
    float4 b4 = *(const float4*)(b_out + e0);
    unsigned long long acc[4][4];
    #pragma unroll
    for (int mp = 0; mp < 4; mp++) {
        float4 ea = ev[2 * mp];
        float4 eb = ev[2 * mp + 1];
        acc[mp][0] = pk2(ea.x + b4.x, eb.x + b4.x);
        acc[mp][1] = pk2(ea.y + b4.y, eb.y + b4.y);
        acc[mp][2] = pk2(ea.z + b4.z, eb.z + b4.z);
        acc[mp][3] = pk2(ea.w + b4.w, eb.w + b4.w);
    }

    // 5) fma mainloop: 16 FFMA2 + 3 LDS per thread per j
    #pragma unroll 8
    for (int j = 0; j < DH; j++) {
        float4 t4 = *(const float4*)(sT + j * DE + e0);
        unsigned long long t0 = pk2(t4.x, t4.x);
        unsigned long long t1 = pk2(t4.y, t4.y);
        unsigned long long t2 = pk2(t4.z, t4.z);
        unsigned long long t3 = pk2(t4.w, t4.w);
        const ulonglong2* rj = (const ulonglong2*)(sR + j * 64 + mt);
        ulonglong2 rA = rj[0];   // m-pairs (0,1),(2,3)  (broadcast LDS)
        ulonglong2 rB = rj[1];   // m-pairs (4,5),(6,7)
        fma2(acc[0][0], rA.x, t0); fma2(acc[0][1], rA.x, t1);
        fma2(acc[0][2], rA.x, t2); fma2(acc[0][3], rA.x, t3);
        fma2(acc[1][0], rA.y, t0); fma2(acc[1][1], rA.y, t1);
        fma2(acc[1][2], rA.y, t2); fma2(acc[1][3], rA.y, t3);
        fma2(acc[2][0], rB.x, t0); fma2(acc[2][1], rB.x, t1);
        fma2(acc[2][2], rB.x, t2); fma2(acc[2][3], rB.x, t3);
        fma2(acc[3][0], rB.y, t0); fma2(acc[3][1], rB.y, t1);
        fma2(acc[3][2], rB.y, t2); fma2(acc[3][3], rB.y, t3);
    }

    // 6) epilogue: streaming STG.128
    float* orow = out + ((size_t)n * NN + m_base + mt) * DE + e0;
    #pragma unroll
    for (int mp = 0; mp < 4; mp++) {
        float a0, c0, a1, c1, a2, c2, a3, c3;
        upk2(acc[mp][0], a0, c0);
        upk2(acc[mp][1], a1, c1);
        upk2(acc[mp][2], a2, c2);
        upk2(acc[mp][3], a3, c3);
        __stcs((float4*)(orow + (2 * mp) * DE),     make_float4(a0, a1, a2, a3));
        __stcs((float4*)(orow + (2 * mp + 1) * DE), make_float4(c0, c1, c2, c3));
    }
}

// ---------------- launch ----------------
extern "C" void kernel_launch(void* const* d_in, const int* in_sizes, int n_in,
                              void* d_out, int out_size) {
    const float* node   = (const float*)d_in[0];
    const float* edge   = (const float*)d_in[1];
    const float* ln_w   = (const float*)d_in[2];
    const float* ln_b   = (const float*)d_in[3];
    const float* w_left = (const float*)d_in[4];
    const float* b_left = (const float*)d_in[5];
    const float* w_right= (const float*)d_in[6];
    const float* b_right= (const float*)d_in[7];
    const float* w_out  = (const float*)d_in[8];
    const float* b_out  = (const float*)d_in[9];
    float* out = (float*)d_out;

    p1_kernel<<<NN, 256>>>(node, ln_w, ln_b, w_left, b_left, w_right, b_right);
    p2_kernel<<<dim3(32, 16), 256>>>(w_out);
    outk_kernel<<<dim3(8, NN), 256>>>(edge, b_out, out);
}